// round 1
// baseline (speedup 1.0000x reference)
#include <cuda_runtime.h>
#include <mma.h>
#include <math.h>

using namespace nvcuda;

#define B_WIN  4096
#define N_WINMASK 64
#define NT     49
#define CDIM   256
#define HEADS  8
#define HDIM   32
#define KQKV   768
#define MROWS  (B_WIN * NT)          /* 200704 = 128*1568 */
#define SCALE_F 0.17677669529663687f /* 32^-0.5 */

/* -------- scratch (allocation-free: __device__ globals) -------- */
__device__ float g_qkv[(size_t)MROWS * KQKV]; /* [m][768]  q|k|v per head */
__device__ float g_o[(size_t)MROWS * CDIM];   /* [m][256]  heads merged   */

/* =====================================================================
 * GEMM: C[m,n] = sum_k A[m,k] * W[n,k] + bias[n]
 * A: [M,K] row-major, W: [N,K] row-major (so C = A @ W^T + b)
 * Block tile 128(M) x 64(N), BK=32, 256 threads = 8 warps (4M x 2N),
 * warp tile 32x32 via tf32 wmma m16n16k8.
 * Requires M % 128 == 0, N % 64 == 0, K % 32 == 0 (true here).
 * ===================================================================*/
__global__ __launch_bounds__(256) void gemm_tf32_kernel(
    const float* __restrict__ A, const float* __restrict__ W,
    const float* __restrict__ bias, float* __restrict__ C,
    int Nld, int K)
{
    __shared__ float smem[8704]; /* max(128*40 + 64*40, 128*68) */
    float* As = smem;            /* [128][40] */
    float* Bs = smem + 128 * 40; /* [64][40]  */

    const int tid  = threadIdx.x;
    const int warp = tid >> 5;
    const int wm   = warp & 3;   /* 0..3 along M */
    const int wn   = warp >> 2;  /* 0..1 along N */
    const int m0   = blockIdx.y * 128;
    const int n0   = blockIdx.x * 64;

    wmma::fragment<wmma::accumulator, 16, 16, 8, float> c[2][2];
#pragma unroll
    for (int i = 0; i < 2; i++)
#pragma unroll
        for (int j = 0; j < 2; j++)
            wmma::fill_fragment(c[i][j], 0.0f);

    for (int kc = 0; kc < K; kc += 32) {
        __syncthreads();
        /* A tile: 128 rows x 32 cols = 1024 float4, 4 per thread */
#pragma unroll
        for (int i = 0; i < 4; i++) {
            int lin = tid + i * 256;
            int row = lin >> 3;
            int c4  = (lin & 7) << 2;
            float4 v = *(const float4*)&A[(size_t)(m0 + row) * K + kc + c4];
            *(float4*)&As[row * 40 + c4] = v;
        }
        /* B tile: 64 rows x 32 cols = 512 float4, 2 per thread */
#pragma unroll
        for (int i = 0; i < 2; i++) {
            int lin = tid + i * 256;
            int row = lin >> 3;
            int c4  = (lin & 7) << 2;
            float4 v = *(const float4*)&W[(size_t)(n0 + row) * K + kc + c4];
            *(float4*)&Bs[row * 40 + c4] = v;
        }
        __syncthreads();

#pragma unroll
        for (int ks = 0; ks < 4; ks++) {
            wmma::fragment<wmma::matrix_a, 16, 16, 8, wmma::precision::tf32,
                           wmma::row_major> a[2];
            wmma::fragment<wmma::matrix_b, 16, 16, 8, wmma::precision::tf32,
                           wmma::col_major> b[2];
#pragma unroll
            for (int i = 0; i < 2; i++) {
                wmma::load_matrix_sync(a[i], &As[(wm * 32 + i * 16) * 40 + ks * 8], 40);
#pragma unroll
                for (int t = 0; t < a[i].num_elements; t++)
                    a[i].x[t] = wmma::__float_to_tf32(a[i].x[t]);
            }
#pragma unroll
            for (int j = 0; j < 2; j++) {
                wmma::load_matrix_sync(b[j], &Bs[(wn * 32 + j * 16) * 40 + ks * 8], 40);
#pragma unroll
                for (int t = 0; t < b[j].num_elements; t++)
                    b[j].x[t] = wmma::__float_to_tf32(b[j].x[t]);
            }
#pragma unroll
            for (int i = 0; i < 2; i++)
#pragma unroll
                for (int j = 0; j < 2; j++)
                    wmma::mma_sync(c[i][j], a[i], b[j], c[i][j]);
        }
    }

    /* epilogue: stage to smem [128][68], then bias + coalesced store */
    __syncthreads();
#pragma unroll
    for (int i = 0; i < 2; i++)
#pragma unroll
        for (int j = 0; j < 2; j++)
            wmma::store_matrix_sync(&smem[(wm * 32 + i * 16) * 68 + wn * 32 + j * 16],
                                    c[i][j], 68, wmma::mem_row_major);
    __syncthreads();
    for (int idx = tid; idx < 128 * 16; idx += 256) {
        int row = idx >> 4;
        int c4  = (idx & 15) << 2;
        float4 v  = *(float4*)&smem[row * 68 + c4];
        float4 bv = *(const float4*)&bias[n0 + c4];
        v.x += bv.x; v.y += bv.y; v.z += bv.z; v.w += bv.w;
        *(float4*)&C[(size_t)(m0 + row) * Nld + n0 + c4] = v;
    }
}

/* =====================================================================
 * Attention kernel: one block per (window b, head h). 128 threads.
 * q,k,v: [49][32] padded into 64-row tiles, S = (SCALE*Q) K^T via tf32
 * wmma on 64x64 tile, + rel-pos bias + window mask, softmax, attn probs
 * written to d_out, then O = P V via tf32 wmma.
 * ===================================================================*/
__global__ __launch_bounds__(128) void attn_kernel(
    const float* __restrict__ qkv, const float* __restrict__ mask,
    const float* __restrict__ bias_table, float* __restrict__ attn_out,
    float* __restrict__ o_out)
{
    __shared__ float qs[64 * 36];
    __shared__ float ks_[64 * 36];
    __shared__ float vs[64 * 36];
    __shared__ float ss[64 * 68];

    const int tid  = threadIdx.x;
    const int warp = tid >> 5;
    const int h    = blockIdx.x;
    const int b    = blockIdx.y;

    /* zero pad regions (zero everything, then overwrite valid part) */
    for (int i = tid; i < 64 * 36; i += 128) { qs[i] = 0.f; ks_[i] = 0.f; vs[i] = 0.f; }
    __syncthreads();

    const float* base = qkv + (size_t)b * NT * KQKV + h * HDIM;
    for (int idx = tid; idx < NT * HDIM; idx += 128) {
        int n = idx >> 5, d = idx & 31;
        size_t off = (size_t)n * KQKV + d;
        qs[n * 36 + d]  = base[off] * SCALE_F;
        ks_[n * 36 + d] = base[off + 256];
        vs[n * 36 + d]  = base[off + 512];
    }
    __syncthreads();

    /* S = Qs * Ks^T  (64x64, K=32). warp -> 16-row slab, 4 col tiles */
    {
        wmma::fragment<wmma::accumulator, 16, 16, 8, float> sc[4];
#pragma unroll
        for (int j = 0; j < 4; j++) wmma::fill_fragment(sc[j], 0.0f);
#pragma unroll
        for (int ks = 0; ks < 4; ks++) {
            wmma::fragment<wmma::matrix_a, 16, 16, 8, wmma::precision::tf32,
                           wmma::row_major> a;
            wmma::load_matrix_sync(a, &qs[(warp * 16) * 36 + ks * 8], 36);
#pragma unroll
            for (int t = 0; t < a.num_elements; t++)
                a.x[t] = wmma::__float_to_tf32(a.x[t]);
#pragma unroll
            for (int j = 0; j < 4; j++) {
                wmma::fragment<wmma::matrix_b, 16, 16, 8, wmma::precision::tf32,
                               wmma::col_major> bfr;
                wmma::load_matrix_sync(bfr, &ks_[(j * 16) * 36 + ks * 8], 36);
#pragma unroll
                for (int t = 0; t < bfr.num_elements; t++)
                    bfr.x[t] = wmma::__float_to_tf32(bfr.x[t]);
                wmma::mma_sync(sc[j], a, bfr, sc[j]);
            }
        }
#pragma unroll
        for (int j = 0; j < 4; j++)
            wmma::store_matrix_sync(&ss[(warp * 16) * 68 + j * 16], sc[j], 68,
                                    wmma::mem_row_major);
    }
    __syncthreads();

    /* bias + mask + stable softmax, one thread per query row */
    if (tid < NT) {
        const int n  = tid;
        const int nh = n / 7, nw = n % 7;
        const float* mrow = mask + (size_t)(b & (N_WINMASK - 1)) * NT * NT + n * NT;
        float mx = -1e30f;
        for (int m = 0; m < NT; m++) {
            int mh = m / 7, mw = m % 7;
            int rel = (nh - mh + 6) * 13 + (nw - mw + 6);
            float t = ss[n * 68 + m] + __ldg(&bias_table[rel * HEADS + h]) + mrow[m];
            ss[n * 68 + m] = t;
            mx = fmaxf(mx, t);
        }
        float sum = 0.f;
        for (int m = 0; m < NT; m++) {
            float e = __expf(ss[n * 68 + m] - mx);
            ss[n * 68 + m] = e;
            sum += e;
        }
        float inv = 1.0f / sum;
        for (int m = 0; m < NT; m++) ss[n * 68 + m] *= inv;
    }
    __syncthreads();

    /* write attention probabilities (coalesced loop) */
    float* aout = attn_out + (size_t)(b * HEADS + h) * NT * NT;
    for (int idx = tid; idx < NT * NT; idx += 128) {
        int n = idx / NT, m = idx - n * NT;
        aout[idx] = ss[n * 68 + m];
    }

    /* O = P(64x64, zero-padded) @ V(64x32). warp -> 16-row slab, 2 col tiles */
    {
        wmma::fragment<wmma::accumulator, 16, 16, 8, float> oc[2];
#pragma unroll
        for (int j = 0; j < 2; j++) wmma::fill_fragment(oc[j], 0.0f);
#pragma unroll
        for (int ks = 0; ks < 8; ks++) {
            wmma::fragment<wmma::matrix_a, 16, 16, 8, wmma::precision::tf32,
                           wmma::row_major> a;
            wmma::load_matrix_sync(a, &ss[(warp * 16) * 68 + ks * 8], 68);
#pragma unroll
            for (int t = 0; t < a.num_elements; t++)
                a.x[t] = wmma::__float_to_tf32(a.x[t]);
#pragma unroll
            for (int j = 0; j < 2; j++) {
                wmma::fragment<wmma::matrix_b, 16, 16, 8, wmma::precision::tf32,
                               wmma::row_major> bfr;
                wmma::load_matrix_sync(bfr, &vs[(ks * 8) * 36 + j * 16], 36);
#pragma unroll
                for (int t = 0; t < bfr.num_elements; t++)
                    bfr.x[t] = wmma::__float_to_tf32(bfr.x[t]);
                wmma::mma_sync(oc[j], a, bfr, oc[j]);
            }
        }
        /* stage to qs (no longer needed), warp-private rows */
#pragma unroll
        for (int j = 0; j < 2; j++)
            wmma::store_matrix_sync(&qs[(warp * 16) * 36 + j * 16], oc[j], 36,
                                    wmma::mem_row_major);
    }
    __syncthreads();

    /* write O rows < 49, merged-head layout [b*49+n][h*32+d] */
    float* obase = o_out + (size_t)b * NT * CDIM + h * HDIM;
    for (int idx = tid; idx < NT * HDIM; idx += 128) {
        int n = idx >> 5, d = idx & 31;
        obase[(size_t)n * CDIM + d] = qs[n * 36 + d];
    }
}

/* ===================================================================*/
extern "C" void kernel_launch(void* const* d_in, const int* in_sizes, int n_in,
                              void* d_out, int out_size)
{
    const float* x          = (const float*)d_in[0];
    const float* mask       = (const float*)d_in[1];
    const float* qkv_w      = (const float*)d_in[2];
    const float* qkv_b      = (const float*)d_in[3];
    const float* proj_w     = (const float*)d_in[4];
    const float* proj_b     = (const float*)d_in[5];
    const float* bias_table = (const float*)d_in[6];

    float* out_part  = (float*)d_out;                       /* [200704][256] */
    float* attn_part = out_part + (size_t)MROWS * CDIM;     /* [32768][49][49] */

    float* qkv_s = nullptr;
    float* o_s   = nullptr;
    cudaGetSymbolAddress((void**)&qkv_s, g_qkv);
    cudaGetSymbolAddress((void**)&o_s, g_o);

    /* 1) QKV GEMM: [200704,256] @ [768,256]^T + b -> g_qkv */
    gemm_tf32_kernel<<<dim3(KQKV / 64, MROWS / 128), 256>>>(
        x, qkv_w, qkv_b, qkv_s, KQKV, CDIM);

    /* 2) per-(window,head) attention */
    attn_kernel<<<dim3(HEADS, B_WIN), 128>>>(
        qkv_s, mask, bias_table, attn_part, o_s);

    /* 3) proj GEMM: [200704,256] @ [256,256]^T + b -> out */
    gemm_tf32_kernel<<<dim3(CDIM / 64, MROWS / 128), 256>>>(
        o_s, proj_w, proj_b, out_part, CDIM, CDIM);
}

// round 2
// speedup vs baseline: 1.0761x; 1.0761x over previous
#include <cuda_runtime.h>
#include <mma.h>
#include <math.h>

using namespace nvcuda;

#define B_WIN  4096
#define NT     49
#define CDIM   256
#define HEADS  8
#define HDIM   32
#define KQKV   768
#define MROWS  (B_WIN * NT)          /* 200704 = 128*1568 */
#define SCALE_F 0.17677669529663687f /* 32^-0.5 */

/* -------- scratch (allocation-free: __device__ globals) -------- */
__device__ float g_qkv[(size_t)MROWS * KQKV]; /* [m][768]  q|k|v per head */
__device__ float g_o[(size_t)MROWS * CDIM];   /* [m][256]  heads merged   */

/* -------- cp.async helpers -------- */
__device__ __forceinline__ void cp_async16(void* smem_dst, const void* gmem_src) {
    unsigned sa = (unsigned)__cvta_generic_to_shared(smem_dst);
    asm volatile("cp.async.cg.shared.global [%0], [%1], 16;\n" :: "r"(sa), "l"(gmem_src));
}
__device__ __forceinline__ void cp_commit() {
    asm volatile("cp.async.commit_group;\n" ::: "memory");
}
template <int N>
__device__ __forceinline__ void cp_wait() {
    asm volatile("cp.async.wait_group %0;\n" :: "n"(N) : "memory");
}

/* =====================================================================
 * GEMM v2: C[m,n] = sum_k A[m,k] * W[n,k] + bias[n]
 * 128(M) x 128(N) block, BK=32, cp.async double buffer.
 * 256 threads = 8 warps laid out 4(M) x 2(N); warp tile 32 x 64 via
 * tf32 wmma m16n16k8. Bias preloaded into accumulators; fragments
 * stored directly to global (no epilogue staging).
 * Requires M%128==0, N%128==0, K%32==0 (true for all uses here).
 * ===================================================================*/
#define GS_STAGE (128 * 40)          /* floats per (A or B) stage */

__global__ __launch_bounds__(256, 2) void gemm2_kernel(
    const float* __restrict__ A, const float* __restrict__ W,
    const float* __restrict__ bias, float* __restrict__ C,
    int Nld, int K)
{
    extern __shared__ float smem[];
    float* As    = smem;                    /* 2 x 128 x 40 */
    float* Bs    = smem + 2 * GS_STAGE;     /* 2 x 128 x 40 */
    float* btile = smem + 4 * GS_STAGE;     /* 16 x 132     */

    const int tid  = threadIdx.x;
    const int warp = tid >> 5;
    const int wm   = warp >> 1;  /* 0..3 along M */
    const int wn   = warp & 1;   /* 0..1 along N */
    const int m0   = blockIdx.y * 128;
    const int n0   = blockIdx.x * 128;

    const int lrow = tid >> 3;        /* 0..31 base row  */
    const int lcol = (tid & 7) << 2;  /* 0..28 col (x4)  */

    const int nk = K >> 5;

    /* issue stage 0 and 1 */
#pragma unroll
    for (int st = 0; st < 2; st++) {
        if (st < nk) {
            int kc = st * 32;
#pragma unroll
            for (int i = 0; i < 4; i++) {
                int row = lrow + i * 32;
                cp_async16(&As[st * GS_STAGE + row * 40 + lcol],
                           &A[(size_t)(m0 + row) * K + kc + lcol]);
                cp_async16(&Bs[st * GS_STAGE + row * 40 + lcol],
                           &W[(size_t)(n0 + row) * K + kc + lcol]);
            }
        }
        cp_commit();
    }

    /* bias tile: 16 identical rows of bias[n0..n0+127] */
    for (int idx = tid; idx < 16 * 128; idx += 256) {
        int row = idx >> 7, col = idx & 127;
        btile[row * 132 + col] = bias[n0 + col];
    }
    __syncthreads();

    /* accumulators preloaded with bias */
    wmma::fragment<wmma::accumulator, 16, 16, 8, float> c[2][4];
#pragma unroll
    for (int j = 0; j < 4; j++) {
        wmma::load_matrix_sync(c[0][j], &btile[wn * 64 + j * 16], 132,
                               wmma::mem_row_major);
        c[1][j] = c[0][j];
    }

    for (int kt = 0; kt < nk; kt++) {
        cp_wait<1>();
        __syncthreads();
        const float* Ab = As + (kt & 1) * GS_STAGE;
        const float* Bb = Bs + (kt & 1) * GS_STAGE;

#pragma unroll
        for (int ks = 0; ks < 4; ks++) {
            wmma::fragment<wmma::matrix_a, 16, 16, 8, wmma::precision::tf32,
                           wmma::row_major> a[2];
            wmma::fragment<wmma::matrix_b, 16, 16, 8, wmma::precision::tf32,
                           wmma::col_major> b[4];
#pragma unroll
            for (int i = 0; i < 2; i++) {
                wmma::load_matrix_sync(a[i], &Ab[(wm * 32 + i * 16) * 40 + ks * 8], 40);
#pragma unroll
                for (int t = 0; t < a[i].num_elements; t++)
                    a[i].x[t] = wmma::__float_to_tf32(a[i].x[t]);
            }
#pragma unroll
            for (int j = 0; j < 4; j++) {
                wmma::load_matrix_sync(b[j], &Bb[(wn * 64 + j * 16) * 40 + ks * 8], 40);
#pragma unroll
                for (int t = 0; t < b[j].num_elements; t++)
                    b[j].x[t] = wmma::__float_to_tf32(b[j].x[t]);
            }
#pragma unroll
            for (int i = 0; i < 2; i++)
#pragma unroll
                for (int j = 0; j < 4; j++)
                    wmma::mma_sync(c[i][j], a[i], b[j], c[i][j]);
        }
        __syncthreads();

        /* refill the buffer we just consumed */
        int kn = kt + 2;
        if (kn < nk) {
            int kc = kn * 32;
            int st = kt & 1;
#pragma unroll
            for (int i = 0; i < 4; i++) {
                int row = lrow + i * 32;
                cp_async16(&As[st * GS_STAGE + row * 40 + lcol],
                           &A[(size_t)(m0 + row) * K + kc + lcol]);
                cp_async16(&Bs[st * GS_STAGE + row * 40 + lcol],
                           &W[(size_t)(n0 + row) * K + kc + lcol]);
            }
        }
        cp_commit();
    }

    /* direct fragment store to global */
#pragma unroll
    for (int i = 0; i < 2; i++)
#pragma unroll
        for (int j = 0; j < 4; j++)
            wmma::store_matrix_sync(
                &C[(size_t)(m0 + wm * 32 + i * 16) * Nld + n0 + wn * 64 + j * 16],
                c[i][j], Nld, wmma::mem_row_major);
}

/* =====================================================================
 * Attention kernel v2: one block per (window b, head h). 128 threads.
 * - q/k/v converted to tf32 at smem-store time (no per-fragment cvt)
 * - bias_table gathered once into smem (169 values for this head)
 * - bias+mask added in a coalesced 128-thread pass
 * - softmax: 2 threads per row + shfl reduce (padded rows do harmless
 *   work so the full-warp shfl mask is valid)
 * ===================================================================*/
__global__ __launch_bounds__(128) void attn_kernel(
    const float* __restrict__ qkv, const float* __restrict__ mask,
    const float* __restrict__ bias_table, float* __restrict__ attn_out,
    float* __restrict__ o_out)
{
    __shared__ float qs[64 * 36];
    __shared__ float ks_[64 * 36];
    __shared__ float vs[64 * 36];
    __shared__ float ss[64 * 68];
    __shared__ float biasS[176];

    const int tid  = threadIdx.x;
    const int warp = tid >> 5;
    const int h    = blockIdx.x;
    const int b    = blockIdx.y;

    /* zero everything (covers padding), gather this head's bias column */
    for (int i = tid; i < 64 * 36; i += 128) { qs[i] = 0.f; ks_[i] = 0.f; vs[i] = 0.f; }
    for (int r = tid; r < 169; r += 128) biasS[r] = __ldg(&bias_table[r * HEADS + h]);
    __syncthreads();

    const float* base = qkv + (size_t)b * NT * KQKV + h * HDIM;
    for (int idx = tid; idx < NT * HDIM; idx += 128) {
        int n = idx >> 5, d = idx & 31;
        size_t off = (size_t)n * KQKV + d;
        qs[n * 36 + d]  = wmma::__float_to_tf32(base[off] * SCALE_F);
        ks_[n * 36 + d] = wmma::__float_to_tf32(base[off + 256]);
        vs[n * 36 + d]  = wmma::__float_to_tf32(base[off + 512]);
    }
    __syncthreads();

    /* S = Qs * Ks^T  (64x64, K=32). warp -> 16-row slab, 4 col tiles */
    {
        wmma::fragment<wmma::accumulator, 16, 16, 8, float> sc[4];
#pragma unroll
        for (int j = 0; j < 4; j++) wmma::fill_fragment(sc[j], 0.0f);
#pragma unroll
        for (int ks = 0; ks < 4; ks++) {
            wmma::fragment<wmma::matrix_a, 16, 16, 8, wmma::precision::tf32,
                           wmma::row_major> a;
            wmma::load_matrix_sync(a, &qs[(warp * 16) * 36 + ks * 8], 36);
#pragma unroll
            for (int j = 0; j < 4; j++) {
                wmma::fragment<wmma::matrix_b, 16, 16, 8, wmma::precision::tf32,
                               wmma::col_major> bfr;
                wmma::load_matrix_sync(bfr, &ks_[(j * 16) * 36 + ks * 8], 36);
                wmma::mma_sync(sc[j], a, bfr, sc[j]);
            }
        }
#pragma unroll
        for (int j = 0; j < 4; j++)
            wmma::store_matrix_sync(&ss[(warp * 16) * 68 + j * 16], sc[j], 68,
                                    wmma::mem_row_major);
    }
    __syncthreads();

    /* coalesced bias + mask add over the 49x49 valid region */
    {
        const float* mwin = mask + (size_t)(b & 63) * NT * NT;
        for (int idx = tid; idx < NT * NT; idx += 128) {
            int n = idx / NT, m = idx - n * NT;
            int nh = n / 7, nw = n - nh * 7;
            int mh = m / 7, mw = m - mh * 7;
            int rel = (nh - mh + 6) * 13 + (nw - mw + 6);
            ss[n * 68 + m] += biasS[rel] + mwin[idx];
        }
    }
    __syncthreads();

    /* softmax: 2 threads per row; rows 49..63 do harmless work on zeros */
    {
        int n = tid >> 1, half = tid & 1;
        float* row = &ss[n * 68];
        float mx = -1e30f;
        for (int m = half; m < NT; m += 2) mx = fmaxf(mx, row[m]);
        mx = fmaxf(mx, __shfl_xor_sync(0xffffffffu, mx, 1));
        float sum = 0.f;
        for (int m = half; m < NT; m += 2) {
            float e = __expf(row[m] - mx);
            row[m] = e;
            sum += e;
        }
        sum += __shfl_xor_sync(0xffffffffu, sum, 1);
        float inv = 1.0f / sum;
        for (int m = half; m < NT; m += 2) row[m] *= inv;
    }
    __syncthreads();

    /* write attention probabilities (coalesced) */
    float* aout = attn_out + (size_t)(b * HEADS + h) * NT * NT;
    for (int idx = tid; idx < NT * NT; idx += 128) {
        int n = idx / NT, m = idx - n * NT;
        aout[idx] = ss[n * 68 + m];
    }

    /* O = P(64x64) @ V(64x32). P fragments need tf32 cvt (probs are fp32) */
    {
        wmma::fragment<wmma::accumulator, 16, 16, 8, float> oc[2];
#pragma unroll
        for (int j = 0; j < 2; j++) wmma::fill_fragment(oc[j], 0.0f);
#pragma unroll
        for (int ks = 0; ks < 8; ks++) {
            wmma::fragment<wmma::matrix_a, 16, 16, 8, wmma::precision::tf32,
                           wmma::row_major> a;
            wmma::load_matrix_sync(a, &ss[(warp * 16) * 68 + ks * 8], 68);
#pragma unroll
            for (int t = 0; t < a.num_elements; t++)
                a.x[t] = wmma::__float_to_tf32(a.x[t]);
#pragma unroll
            for (int j = 0; j < 2; j++) {
                wmma::fragment<wmma::matrix_b, 16, 16, 8, wmma::precision::tf32,
                               wmma::row_major> bfr;
                wmma::load_matrix_sync(bfr, &vs[(ks * 8) * 36 + j * 16], 36);
                wmma::mma_sync(oc[j], a, bfr, oc[j]);
            }
        }
#pragma unroll
        for (int j = 0; j < 2; j++)
            wmma::store_matrix_sync(&qs[(warp * 16) * 36 + j * 16], oc[j], 36,
                                    wmma::mem_row_major);
    }
    __syncthreads();

    /* write O rows < 49, merged-head layout [b*49+n][h*32+d] */
    float* obase = o_out + (size_t)b * NT * CDIM + h * HDIM;
    for (int idx = tid; idx < NT * HDIM; idx += 128) {
        int n = idx >> 5, d = idx & 31;
        obase[(size_t)n * CDIM + d] = qs[n * 36 + d];
    }
}

/* ===================================================================*/
#define GEMM2_SMEM ((4 * GS_STAGE + 16 * 132) * (int)sizeof(float))

extern "C" void kernel_launch(void* const* d_in, const int* in_sizes, int n_in,
                              void* d_out, int out_size)
{
    const float* x          = (const float*)d_in[0];
    const float* mask       = (const float*)d_in[1];
    const float* qkv_w      = (const float*)d_in[2];
    const float* qkv_b      = (const float*)d_in[3];
    const float* proj_w     = (const float*)d_in[4];
    const float* proj_b     = (const float*)d_in[5];
    const float* bias_table = (const float*)d_in[6];

    float* out_part  = (float*)d_out;                       /* [200704][256] */
    float* attn_part = out_part + (size_t)MROWS * CDIM;     /* [32768][49][49] */

    float* qkv_s = nullptr;
    float* o_s   = nullptr;
    cudaGetSymbolAddress((void**)&qkv_s, g_qkv);
    cudaGetSymbolAddress((void**)&o_s, g_o);

    static int smem_set = 0;
    if (!smem_set) {
        cudaFuncSetAttribute(gemm2_kernel,
                             cudaFuncAttributeMaxDynamicSharedMemorySize,
                             GEMM2_SMEM);
        smem_set = 1;
    }

    /* 1) QKV GEMM: [200704,256] @ [768,256]^T + b -> g_qkv */
    gemm2_kernel<<<dim3(KQKV / 128, MROWS / 128), 256, GEMM2_SMEM>>>(
        x, qkv_w, qkv_b, qkv_s, KQKV, CDIM);

    /* 2) per-(window,head) attention */
    attn_kernel<<<dim3(HEADS, B_WIN), 128>>>(
        qkv_s, mask, bias_table, attn_part, o_s);

    /* 3) proj GEMM: [200704,256] @ [256,256]^T + b -> out */
    gemm2_kernel<<<dim3(CDIM / 128, MROWS / 128), 256, GEMM2_SMEM>>>(
        o_s, proj_w, proj_b, out_part, CDIM, CDIM);
}

// round 4
// speedup vs baseline: 2.5353x; 2.3560x over previous
#include <cuda_runtime.h>
#include <cuda_fp16.h>
#include <mma.h>
#include <math.h>
#include <stdint.h>

using namespace nvcuda;

#define B_WIN  4096
#define NT     49
#define CDIM   256
#define HEADS  8
#define HDIM   32
#define KQKV   768
#define MROWS  (B_WIN * NT)          /* 200704 = 128*1568 */
#define SCALE_F 0.17677669529663687f /* 32^-0.5 */

/* -------- scratch (allocation-free: __device__ globals) -------- */
__device__ __half g_xh[(size_t)MROWS * CDIM];    /* x in fp16            */
__device__ __half g_qkvh[(size_t)MROWS * KQKV];  /* qkv in fp16          */
__device__ __half g_oh[(size_t)MROWS * CDIM];    /* attn out in fp16     */
__device__ __half g_wh[(size_t)KQKV * CDIM];     /* qkv_w fp16           */
__device__ __half g_pwh[(size_t)CDIM * CDIM];    /* proj_w fp16          */

/* -------- cp.async helpers -------- */
__device__ __forceinline__ void cp_async16(void* smem_dst, const void* gmem_src) {
    unsigned sa = (unsigned)__cvta_generic_to_shared(smem_dst);
    asm volatile("cp.async.cg.shared.global [%0], [%1], 16;\n" :: "r"(sa), "l"(gmem_src));
}
__device__ __forceinline__ void cp_commit() {
    asm volatile("cp.async.commit_group;\n" ::: "memory");
}
template <int N>
__device__ __forceinline__ void cp_wait() {
    asm volatile("cp.async.wait_group %0;\n" :: "n"(N) : "memory");
}

/* =====================================================================
 * fp32 -> fp16 convert (vectorized, n % 4 == 0)
 * ===================================================================*/
__global__ __launch_bounds__(256) void f2h_kernel(
    const float* __restrict__ in, __half* __restrict__ out, int n)
{
    int i = (blockIdx.x * 256 + threadIdx.x) * 4;
    if (i < n) {
        float4 v = *(const float4*)&in[i];
        half2 h0 = __floats2half2_rn(v.x, v.y);
        half2 h1 = __floats2half2_rn(v.z, v.w);
        *(half2*)&out[i]     = h0;
        *(half2*)&out[i + 2] = h1;
    }
}

/* =====================================================================
 * GEMM v3 (fp16 HMMA): C[m,n] = sum_k A[m,k]*W[n,k] + bias[n]
 * A: [M,K] fp16 row-major, W: [N,K] fp16 row-major, bias fp32.
 * Block 128x128, BK=64, cp.async double buffer, 256 thr = 8 warps
 * (4M x 2N), warp tile 32x64 via wmma m16n16k16 fp16->fp32.
 * OUT_HALF=1: stage + convert to fp16.  OUT_HALF=0: direct fp32 store.
 * Requires M%128==0, N%128==0, K%64==0.
 * ===================================================================*/
#define HS_TILE  (128 * 72)               /* halves per operand stage  */
#define HS_STAGE (2 * HS_TILE)            /* halves per (A+B) stage    */
#define GEMMH_SMEM (2 * HS_STAGE * 2 + 16 * 132 * 4 + 256)

template <int OUT_HALF>
__global__ __launch_bounds__(256) void gemm_h_kernel(
    const __half* __restrict__ A, const __half* __restrict__ W,
    const float* __restrict__ bias, void* __restrict__ Cv,
    int Nld, int K)
{
    extern __shared__ char smem_raw[];
    __half* Ah = (__half*)smem_raw;                 /* stage s: Ah + s*HS_STAGE     */
    float*  btile = (float*)(smem_raw + 2 * HS_STAGE * 2); /* 16 x 132 */

    const int tid  = threadIdx.x;
    const int warp = tid >> 5;
    const int wm   = warp >> 1;  /* 0..3 along M */
    const int wn   = warp & 1;   /* 0..1 along N */
    const int m0   = blockIdx.y * 128;
    const int n0   = blockIdx.x * 128;
    const int nk   = K >> 6;

    const int cr = tid >> 3;       /* base row 0..31     */
    const int cc = tid & 7;        /* 16B chunk (8 halves) */

    /* issue stage 0 and 1 */
#pragma unroll
    for (int st = 0; st < 2; st++) {
        if (st < nk) {
            int kc = st * 64;
#pragma unroll
            for (int i = 0; i < 4; i++) {
                int r = cr + i * 32;
                cp_async16(&Ah[st * HS_STAGE + r * 72 + cc * 8],
                           &A[(size_t)(m0 + r) * K + kc + cc * 8]);
                cp_async16(&Ah[st * HS_STAGE + HS_TILE + r * 72 + cc * 8],
                           &W[(size_t)(n0 + r) * K + kc + cc * 8]);
            }
        }
        cp_commit();
    }

    /* bias tile: 16 identical rows */
    for (int idx = tid; idx < 16 * 128; idx += 256) {
        int row = idx >> 7, col = idx & 127;
        btile[row * 132 + col] = bias[n0 + col];
    }
    __syncthreads();

    wmma::fragment<wmma::accumulator, 16, 16, 16, float> c[2][4];
#pragma unroll
    for (int j = 0; j < 4; j++) {
        wmma::load_matrix_sync(c[0][j], &btile[wn * 64 + j * 16], 132,
                               wmma::mem_row_major);
        c[1][j] = c[0][j];
    }

    for (int kt = 0; kt < nk; kt++) {
        cp_wait<1>();
        __syncthreads();
        const __half* Ab = Ah + (kt & 1) * HS_STAGE;
        const __half* Bb = Ab + HS_TILE;

#pragma unroll
        for (int ks = 0; ks < 4; ks++) {
            wmma::fragment<wmma::matrix_a, 16, 16, 16, __half, wmma::row_major> a[2];
#pragma unroll
            for (int i = 0; i < 2; i++)
                wmma::load_matrix_sync(a[i], &Ab[(wm * 32 + i * 16) * 72 + ks * 16], 72);
#pragma unroll
            for (int j = 0; j < 4; j++) {
                wmma::fragment<wmma::matrix_b, 16, 16, 16, __half, wmma::col_major> b;
                wmma::load_matrix_sync(b, &Bb[(wn * 64 + j * 16) * 72 + ks * 16], 72);
                wmma::mma_sync(c[0][j], a[0], b, c[0][j]);
                wmma::mma_sync(c[1][j], a[1], b, c[1][j]);
            }
        }
        __syncthreads();

        int kn = kt + 2;
        if (kn < nk) {
            int kc = kn * 64, st = kt & 1;
#pragma unroll
            for (int i = 0; i < 4; i++) {
                int r = cr + i * 32;
                cp_async16(&Ah[st * HS_STAGE + r * 72 + cc * 8],
                           &A[(size_t)(m0 + r) * K + kc + cc * 8]);
                cp_async16(&Ah[st * HS_STAGE + HS_TILE + r * 72 + cc * 8],
                           &W[(size_t)(n0 + r) * K + kc + cc * 8]);
            }
        }
        cp_commit();
    }

    if (OUT_HALF) {
        /* stage fp32 accums to smem, convert to fp16 coalesced */
        float* stg = (float*)smem_raw;   /* 128 x 132 floats, fits in stages */
        __syncthreads();
#pragma unroll
        for (int i = 0; i < 2; i++)
#pragma unroll
            for (int j = 0; j < 4; j++)
                wmma::store_matrix_sync(
                    &stg[(wm * 32 + i * 16) * 132 + wn * 64 + j * 16],
                    c[i][j], 132, wmma::mem_row_major);
        __syncthreads();
        __half* Ch = (__half*)Cv;
        for (int idx = tid; idx < 128 * 64; idx += 256) {
            int row = idx >> 6, cp2 = (idx & 63) << 1;
            half2 h = __floats2half2_rn(stg[row * 132 + cp2],
                                        stg[row * 132 + cp2 + 1]);
            *(half2*)&Ch[(size_t)(m0 + row) * Nld + n0 + cp2] = h;
        }
    } else {
        float* Cf = (float*)Cv;
#pragma unroll
        for (int i = 0; i < 2; i++)
#pragma unroll
            for (int j = 0; j < 4; j++)
                wmma::store_matrix_sync(
                    &Cf[(size_t)(m0 + wm * 32 + i * 16) * Nld + n0 + wn * 64 + j * 16],
                    c[i][j], Nld, wmma::mem_row_major);
    }
}

/* =====================================================================
 * Attention v3 (fp16 HMMA): one block per (window b, head h), 128 thr.
 * S = Q K^T (fp16 mma, fp32 accum); attn = S*scale + bias + mask;
 * softmax fp32; P -> fp16; O = P V (fp16 mma); O stored fp16.
 * ===================================================================*/
__global__ __launch_bounds__(128) void attn_kernel(
    const __half* __restrict__ qkv, const float* __restrict__ mask,
    const float* __restrict__ bias_table, float* __restrict__ attn_out,
    __half* __restrict__ o_out)
{
    __shared__ __half qs[64 * 40];
    __shared__ __half ks_[64 * 40];
    __shared__ __half vs[64 * 40];
    __shared__ float  ss[64 * 68];
    __shared__ __half ps[64 * 72];
    __shared__ float  biasS[176];

    const int tid  = threadIdx.x;
    const int warp = tid >> 5;
    const int h    = blockIdx.x;
    const int b    = blockIdx.y;

    /* zero q/k/v pad regions; gather this head's bias column */
    {
        half2 z = __floats2half2_rn(0.f, 0.f);
        half2* q2 = (half2*)qs; half2* k2 = (half2*)ks_; half2* v2 = (half2*)vs;
        for (int i = tid; i < 64 * 20; i += 128) { q2[i] = z; k2[i] = z; v2[i] = z; }
    }
    for (int r = tid; r < 169; r += 128) biasS[r] = __ldg(&bias_table[r * HEADS + h]);
    __syncthreads();

    /* load q/k/v (half2): 49 rows x 16 half2 */
    {
        const __half* base = qkv + (size_t)b * NT * KQKV + h * HDIM;
        half2* q2 = (half2*)qs; half2* k2 = (half2*)ks_; half2* v2 = (half2*)vs;
        for (int idx = tid; idx < NT * 16; idx += 128) {
            int n = idx >> 4, d2 = idx & 15;
            const half2* src = (const half2*)(base + (size_t)n * KQKV) + d2;
            q2[n * 20 + d2] = src[0];
            k2[n * 20 + d2] = src[128];   /* +256 halves */
            v2[n * 20 + d2] = src[256];   /* +512 halves */
        }
    }
    __syncthreads();

    /* S = Q K^T (64x64, K=32 -> 2 k-steps) */
    {
        wmma::fragment<wmma::accumulator, 16, 16, 16, float> sc[4];
#pragma unroll
        for (int j = 0; j < 4; j++) wmma::fill_fragment(sc[j], 0.0f);
#pragma unroll
        for (int ks = 0; ks < 2; ks++) {
            wmma::fragment<wmma::matrix_a, 16, 16, 16, __half, wmma::row_major> a;
            wmma::load_matrix_sync(a, &qs[(warp * 16) * 40 + ks * 16], 40);
#pragma unroll
            for (int j = 0; j < 4; j++) {
                wmma::fragment<wmma::matrix_b, 16, 16, 16, __half, wmma::col_major> bfr;
                wmma::load_matrix_sync(bfr, &ks_[(j * 16) * 40 + ks * 16], 40);
                wmma::mma_sync(sc[j], a, bfr, sc[j]);
            }
        }
#pragma unroll
        for (int j = 0; j < 4; j++)
            wmma::store_matrix_sync(&ss[(warp * 16) * 68 + j * 16], sc[j], 68,
                                    wmma::mem_row_major);
    }
    __syncthreads();

    /* attn = S*scale + bias + mask over 49x49 valid region */
    {
        const float* mwin = mask + (size_t)(b & 63) * NT * NT;
        for (int idx = tid; idx < NT * NT; idx += 128) {
            int n = idx / NT, m = idx - n * NT;
            int nh = n / 7, nw = n - nh * 7;
            int mh = m / 7, mw = m - mh * 7;
            int rel = (nh - mh + 6) * 13 + (nw - mw + 6);
            ss[n * 68 + m] = ss[n * 68 + m] * SCALE_F + biasS[rel] + mwin[idx];
        }
    }
    __syncthreads();

    /* softmax: 2 threads per row (padded rows do harmless work) */
    {
        int n = tid >> 1, half = tid & 1;
        float* row = &ss[n * 68];
        float mx = -1e30f;
        for (int m = half; m < NT; m += 2) mx = fmaxf(mx, row[m]);
        mx = fmaxf(mx, __shfl_xor_sync(0xffffffffu, mx, 1));
        float sum = 0.f;
        for (int m = half; m < NT; m += 2) {
            float e = __expf(row[m] - mx);
            row[m] = e;
            sum += e;
        }
        sum += __shfl_xor_sync(0xffffffffu, sum, 1);
        float inv = 1.0f / sum;
        for (int m = half; m < NT; m += 2) row[m] *= inv;
    }
    __syncthreads();

    /* write attn probs (fp32) + build fp16 P tile */
    {
        float* aout = attn_out + (size_t)(b * HEADS + h) * NT * NT;
        for (int idx = tid; idx < NT * NT; idx += 128) {
            int n = idx / NT, m = idx - n * NT;
            aout[idx] = ss[n * 68 + m];
        }
        for (int idx = tid; idx < 64 * 32; idx += 128) {
            int n = idx >> 5, m2 = (idx & 31) << 1;
            half2 h2 = __floats2half2_rn(ss[n * 68 + m2], ss[n * 68 + m2 + 1]);
            *(half2*)&ps[n * 72 + m2] = h2;
        }
    }
    __syncthreads();

    /* O = P(64x64) @ V(64x32): 4 k-steps of 16 */
    {
        wmma::fragment<wmma::accumulator, 16, 16, 16, float> oc[2];
#pragma unroll
        for (int j = 0; j < 2; j++) wmma::fill_fragment(oc[j], 0.0f);
#pragma unroll
        for (int ks = 0; ks < 4; ks++) {
            wmma::fragment<wmma::matrix_a, 16, 16, 16, __half, wmma::row_major> a;
            wmma::load_matrix_sync(a, &ps[(warp * 16) * 72 + ks * 16], 72);
#pragma unroll
            for (int j = 0; j < 2; j++) {
                wmma::fragment<wmma::matrix_b, 16, 16, 16, __half, wmma::row_major> bfr;
                wmma::load_matrix_sync(bfr, &vs[(ks * 16) * 40 + j * 16], 40);
                wmma::mma_sync(oc[j], a, bfr, oc[j]);
            }
        }
        /* stage to ss (free now), then fp16 store */
#pragma unroll
        for (int j = 0; j < 2; j++)
            wmma::store_matrix_sync(&ss[(warp * 16) * 68 + j * 16], oc[j], 68,
                                    wmma::mem_row_major);
    }
    __syncthreads();

    {
        __half* obase = o_out + (size_t)b * NT * CDIM + h * HDIM;
        for (int idx = tid; idx < NT * 16; idx += 128) {
            int n = idx >> 4, d2 = (idx & 15) << 1;
            half2 h2 = __floats2half2_rn(ss[n * 68 + d2], ss[n * 68 + d2 + 1]);
            *(half2*)&obase[(size_t)n * CDIM + d2] = h2;
        }
    }
}

/* ===================================================================*/
extern "C" void kernel_launch(void* const* d_in, const int* in_sizes, int n_in,
                              void* d_out, int out_size)
{
    const float* x          = (const float*)d_in[0];
    const float* mask       = (const float*)d_in[1];
    const float* qkv_w      = (const float*)d_in[2];
    const float* qkv_b      = (const float*)d_in[3];
    const float* proj_w     = (const float*)d_in[4];
    const float* proj_b     = (const float*)d_in[5];
    const float* bias_table = (const float*)d_in[6];

    float* out_part  = (float*)d_out;                       /* [200704][256] */
    float* attn_part = out_part + (size_t)MROWS * CDIM;     /* [32768][49][49] */

    __half *xh = nullptr, *qkvh = nullptr, *oh = nullptr, *wh = nullptr, *pwh = nullptr;
    cudaGetSymbolAddress((void**)&xh,   g_xh);
    cudaGetSymbolAddress((void**)&qkvh, g_qkvh);
    cudaGetSymbolAddress((void**)&oh,   g_oh);
    cudaGetSymbolAddress((void**)&wh,   g_wh);
    cudaGetSymbolAddress((void**)&pwh,  g_pwh);

    static int smem_set = 0;
    if (!smem_set) {
        cudaFuncSetAttribute(gemm_h_kernel<1>,
                             cudaFuncAttributeMaxDynamicSharedMemorySize, GEMMH_SMEM);
        cudaFuncSetAttribute(gemm_h_kernel<0>,
                             cudaFuncAttributeMaxDynamicSharedMemorySize, GEMMH_SMEM);
        smem_set = 1;
    }

    /* 0) fp16 conversions */
    f2h_kernel<<<(MROWS * CDIM / 4 + 255) / 256, 256>>>(x, xh, MROWS * CDIM);
    f2h_kernel<<<(KQKV * CDIM / 4 + 255) / 256, 256>>>(qkv_w, wh, KQKV * CDIM);
    f2h_kernel<<<(CDIM * CDIM / 4 + 255) / 256, 256>>>(proj_w, pwh, CDIM * CDIM);

    /* 1) QKV GEMM: [200704,256] @ [768,256]^T + b -> g_qkvh (fp16) */
    gemm_h_kernel<1><<<dim3(KQKV / 128, MROWS / 128), 256, GEMMH_SMEM>>>(
        xh, wh, qkv_b, qkvh, KQKV, CDIM);

    /* 2) per-(window,head) attention */
    attn_kernel<<<dim3(HEADS, B_WIN), 128>>>(
        qkvh, mask, bias_table, attn_part, oh);

    /* 3) proj GEMM: [200704,256] @ [256,256]^T + b -> out (fp32) */
    gemm_h_kernel<0><<<dim3(CDIM / 128, MROWS / 128), 256, GEMMH_SMEM>>>(
        oh, pwh, proj_b, out_part, CDIM, CDIM);
}